// round 15
// baseline (speedup 1.0000x reference)
#include <cuda_runtime.h>
#include <cstdint>
#include <math.h>

#define BATCH 512
#define NNODE 200
#define INC   200
#define HIDC  256
#define NVARS 2
#define NN2   (NNODE * NNODE)   // 40000

// ---------------- scratch ---------------------------------------------------
__device__ float d_mask[NN2];          // (raw+raw^T)/2 + I
__device__ float d_t2[HIDC * NVARS];   // W2 @ pw
__device__ float d_t1[HIDC * NVARS];   // W1 @ t2
__device__ float d_wf[INC * NVARS];    // W0 @ t1   [200,2]
__device__ unsigned d_f1, d_f2, d_f3;  // phase flags (reset by last block)

// ---------------------------------------------------------------------------
__device__ __forceinline__ float sigv(float x) {
    if (x == 0.0f || x == 1.0f)
        return 0.5f + 0.2310585786300049f * x;   // exact {sig(0), sig(1)}
    return 1.0f / (1.0f + __expf(-x));
}

// warp-per-row GEMV row: s[v] = sum_k W[r*K+k] * vin[k*2+v], K=256
__device__ __forceinline__ void gemv_row(const float* __restrict__ W,
                                         const float* __restrict__ vin,
                                         float* __restrict__ vout,
                                         int r, int lane) {
    float s0 = 0.0f, s1 = 0.0f;
#pragma unroll
    for (int i = 0; i < HIDC / 32; i++) {
        int k = lane + i * 32;
        float w = W[(size_t)r * HIDC + k];
        s0 += w * vin[k * 2 + 0];
        s1 += w * vin[k * 2 + 1];
    }
#pragma unroll
    for (int off = 16; off > 0; off >>= 1) {
        s0 += __shfl_down_sync(0xFFFFFFFFu, s0, off);
        s1 += __shfl_down_sync(0xFFFFFFFFu, s1, off);
    }
    if (lane == 0) { vout[r * 2 + 0] = s0; vout[r * 2 + 1] = s1; }
}

__device__ __forceinline__ void spin_until(unsigned* flag, unsigned target,
                                           int tid) {
    if (tid == 0) {
        while (atomicAdd(flag, 0u) < target) { }
        __threadfence();
    }
    __syncthreads();
}

// ---------------------------------------------------------------------------
// prep: 63 co-resident blocks.
//   0..39  : mask = (raw+raw^T)/2 + I
//   40..47 : t2 = W2 @ pw        -> bump d_f1
//   48..55 : spin d_f1==8; t1 = W1 @ t2  -> bump d_f2
//   56..62 : spin d_f2==8; wf = W0 @ t1  -> bump d_f3; last resets flags
// ---------------------------------------------------------------------------
__global__ __launch_bounds__(1024) void prep_kernel(
    const float* __restrict__ raw,
    const float* __restrict__ W0, const float* __restrict__ W1,
    const float* __restrict__ W2, const float* __restrict__ pw)
{
    int tid = threadIdx.x, warp = tid >> 5, lane = tid & 31;
    int blk = blockIdx.x;

    if (blk < 40) {
        int i = blk * 1024 + tid;
        if (i < NN2) {
            int r = i / NNODE, c = i % NNODE;
            float v = 0.5f * (raw[r * NNODE + c] + raw[c * NNODE + r]);
            if (r == c) v += 1.0f;
            d_mask[i] = v;
        }
        return;
    }
    if (blk < 48) {                       // phase A: t2 = W2 @ pw (256 rows)
        int r = (blk - 40) * 32 + warp;
        gemv_row(W2, pw, d_t2, r, lane);
        __threadfence();
        __syncthreads();
        if (tid == 0) atomicAdd(&d_f1, 1u);
        return;
    }
    if (blk < 56) {                       // phase B: t1 = W1 @ t2
        spin_until(&d_f1, 8u, tid);
        int r = (blk - 48) * 32 + warp;
        gemv_row(W1, d_t2, d_t1, r, lane);
        __threadfence();
        __syncthreads();
        if (tid == 0) atomicAdd(&d_f2, 1u);
        return;
    }
    // phase C: wf = W0 @ t1 (200 rows over 7 blocks)
    spin_until(&d_f2, 8u, tid);
    int r = (blk - 56) * 32 + warp;
    if (r < INC) gemv_row(W0, d_t1, d_wf, r, lane);
    __threadfence();
    __syncthreads();
    if (tid == 0) {
        unsigned old = atomicAdd(&d_f3, 1u);
        if (old == 6u) {                  // last of 7: reset for graph replay
            atomicExch(&d_f1, 0u);
            atomicExch(&d_f2, 0u);
            atomicExch(&d_f3, 0u);
        }
    }
}

// ---------------------------------------------------------------------------
// per-batch mega kernel:
//   warps 0..15 : stage A = mask .* sigv(adj_b) into smem (160 KB)
//   warps 16..31: y[n][v] = sum_f F_b[n][f] * wf[f][v]  (concurrent DRAM)
//   then v1 = colsum(A)/200; v2 = v1^T A; v3 = v2^T A
//   out[b][v] = sum_n v3[n]*y[n][v] + pb[v]
// ---------------------------------------------------------------------------
__global__ __launch_bounds__(1024, 1) void adj_kernel(
    const float* __restrict__ adj, const float* __restrict__ feat,
    const float* __restrict__ pb, float* __restrict__ out)
{
    extern __shared__ float sA[];                 // [NN2] 160000 B
    __shared__ float spart[1024];
    __shared__ float sv1[NNODE], sv2[NNODE], sv3[NNODE];
    __shared__ float2 sy[NNODE];

    int tid = threadIdx.x, lane = tid & 31;
    int b = blockIdx.x;

    if (tid < 512) {
        // ---- stage A = mask .* sigv(adj_b), 512 threads, unroll-5 MLP ----
        const float4* A4 = (const float4*)(adj + (size_t)b * NN2);
        const float4* M4 = (const float4*)d_mask;
        float4* S4 = (float4*)sA;
        const int Q4 = NN2 / 4;                   // 10000
#pragma unroll 1
        for (int base = 0; base < Q4; base += 5 * 512) {
            float4 xa[5], xm[5];
#pragma unroll
            for (int q = 0; q < 5; q++) {
                int i = base + tid + q * 512;
                if (i < Q4) { xa[q] = A4[i]; xm[q] = M4[i]; }
            }
#pragma unroll
            for (int q = 0; q < 5; q++) {
                int i = base + tid + q * 512;
                if (i < Q4) {
                    float4 r;
                    r.x = xm[q].x * sigv(xa[q].x);
                    r.y = xm[q].y * sigv(xa[q].y);
                    r.z = xm[q].z * sigv(xa[q].z);
                    r.w = xm[q].w * sigv(xa[q].w);
                    S4[i] = r;
                }
            }
        }
    } else {
        // ---- y-pass: warps 16..31, warp-per-row over F_b ----
        int wy = (tid >> 5) - 16;                 // 0..15
        const float* Fb = feat + (size_t)b * NN2;
        const float2* wf2 = (const float2*)d_wf;
        for (int n = wy; n < NNODE; n += 16) {
            const float* Fr = Fb + (size_t)n * INC;
            float s0 = 0.0f, s1 = 0.0f;
#pragma unroll
            for (int i = 0; i < 7; i++) {
                int f = lane + i * 32;
                if (f < INC) {
                    float fv = Fr[f];
                    float2 w = __ldg(&wf2[f]);
                    s0 += fv * w.x; s1 += fv * w.y;
                }
            }
#pragma unroll
            for (int off = 16; off > 0; off >>= 1) {
                s0 += __shfl_down_sync(0xFFFFFFFFu, s0, off);
                s1 += __shfl_down_sync(0xFFFFFFFFu, s1, off);
            }
            if (lane == 0) sy[n] = make_float2(s0, s1);
        }
    }
    __syncthreads();

    const int g = tid >> 8;         // row-chunk 0..3 (50 rows each)
    const int col = tid & 255;
    const int n0 = g * 50;

    // ---- v1 = colsum/200 ----
    {
        float s = 0;
        if (col < NNODE) {
#pragma unroll 10
            for (int n = 0; n < 50; n++) s += sA[(n0 + n) * NNODE + col];
        }
        spart[(g << 8) + col] = s;
        __syncthreads();
        if (tid < NNODE)
            sv1[tid] = (spart[tid] + spart[256 + tid] + spart[512 + tid] + spart[768 + tid])
                       * (1.0f / NNODE);
        __syncthreads();
    }
    // ---- v2 = v1^T A ----
    {
        float s = 0;
        if (col < NNODE) {
#pragma unroll 10
            for (int n = 0; n < 50; n++) s += sv1[n0 + n] * sA[(n0 + n) * NNODE + col];
        }
        spart[(g << 8) + col] = s;
        __syncthreads();
        if (tid < NNODE)
            sv2[tid] = spart[tid] + spart[256 + tid] + spart[512 + tid] + spart[768 + tid];
        __syncthreads();
    }
    // ---- v3 = v2^T A ----
    {
        float s = 0;
        if (col < NNODE) {
#pragma unroll 10
            for (int n = 0; n < 50; n++) s += sv2[n0 + n] * sA[(n0 + n) * NNODE + col];
        }
        spart[(g << 8) + col] = s;
        __syncthreads();
        if (tid < NNODE)
            sv3[tid] = spart[tid] + spart[256 + tid] + spart[512 + tid] + spart[768 + tid];
        __syncthreads();
    }

    // ---- out = sum_n v3[n] * y[n] + pb ----
    float p0 = 0, p1 = 0;
    if (tid < NNODE) {
        float2 yv = sy[tid];
        p0 = sv3[tid] * yv.x;
        p1 = sv3[tid] * yv.y;
    }
    if (tid < 256) { spart[tid] = p0; spart[256 + tid] = p1; }
    __syncthreads();
#pragma unroll
    for (int off = 128; off > 0; off >>= 1) {
        if (tid < off) {
            spart[tid] += spart[tid + off];
            spart[256 + tid] += spart[256 + tid + off];
        }
        __syncthreads();
    }
    if (tid == 0) {
        out[b * NVARS + 0] = spart[0] + pb[0];
        out[b * NVARS + 1] = spart[256] + pb[1];
    }
}

// ---------------------------------------------------------------------------
extern "C" void kernel_launch(void* const* d_in, const int* in_sizes, int n_in,
                              void* d_out, int out_size)
{
    const float* adj      = (const float*)d_in[0];
    const float* features = (const float*)d_in[1];
    const float* raw      = (const float*)d_in[2];
    const float* W0       = (const float*)d_in[3];
    const float* W1       = (const float*)d_in[4];
    const float* W2       = (const float*)d_in[5];
    const float* pw       = (const float*)d_in[6];
    const float* pb       = (const float*)d_in[7];
    float* out = (float*)d_out;

    const int SMEM_A = NN2 * (int)sizeof(float);   // 160000 B
    cudaFuncSetAttribute(adj_kernel,
                         cudaFuncAttributeMaxDynamicSharedMemorySize, SMEM_A);

    prep_kernel<<<63, 1024>>>(raw, W0, W1, W2, pw);
    adj_kernel<<<BATCH, 1024, SMEM_A>>>(adj, features, pb, out);
}